// round 9
// baseline (speedup 1.0000x reference)
#include <cuda_runtime.h>
#include <cuda_fp16.h>
#include <stdint.h>
#include <stddef.h>

// ---------------------------------------------------------------------------
// out0 = normalize_rows(x) @ features^T   [2048 x 100000]  (fp32)
// out1 = features (passthrough)           [100000 x 256]
// Round 8: fp16 mma.sync GEMM, BM=128 x BN=256, 512 threads, 4 smem stages
// (= NCHUNK, no recycling -> 1 barrier/chunk), half the CTAs of R7.
// ---------------------------------------------------------------------------

#define MROWS 2048
#define KDIM  256
#define NPAD  100096      // 391 * 256

#define BM 128
#define BN 256
#define BK 64
#define NCHUNK 4          // K / BK
#define NSTAGE 4

// smem per stage: A [128][64] fp16 = 16KB, B [256][64] fp16 = 32KB
#define T_A 0
#define T_B 16384
#define STAGE 49152
#define SMEM_TOTAL (NSTAGE * STAGE)   // 192 KB

__device__ __half g_A[MROWS * KDIM];
__device__ __half g_B[(size_t)NPAD * KDIM];

// ------------------------------ helpers -----------------------------------

__device__ __forceinline__ uint32_t smem_u32(const void* p) {
    uint32_t a;
    asm("{ .reg .u64 t; cvta.to.shared.u64 t, %1; cvt.u32.u64 %0, t; }"
        : "=r"(a) : "l"(p));
    return a;
}

__device__ __forceinline__ void cp16(uint32_t dst, const void* src) {
    asm volatile("cp.async.cg.shared.global [%0], [%1], 16;"
                 :: "r"(dst), "l"(src) : "memory");
}
__device__ __forceinline__ void cp_commit() {
    asm volatile("cp.async.commit_group;" ::: "memory");
}

__device__ __forceinline__ void ldmx4(uint32_t* f, uint32_t addr) {
    asm volatile("ldmatrix.sync.aligned.m8n8.x4.shared.b16 {%0,%1,%2,%3}, [%4];"
                 : "=r"(f[0]), "=r"(f[1]), "=r"(f[2]), "=r"(f[3]) : "r"(addr));
}

#define MMA(c, a, b)                                                          \
    asm volatile(                                                             \
        "mma.sync.aligned.m16n8k16.row.col.f32.f16.f16.f32 "                  \
        "{%0,%1,%2,%3},{%4,%5,%6,%7},{%8,%9},{%0,%1,%2,%3};"                  \
        : "+f"((c)[0]), "+f"((c)[1]), "+f"((c)[2]), "+f"((c)[3])              \
        : "r"((a)[0]), "r"((a)[1]), "r"((a)[2]), "r"((a)[3]),                 \
          "r"((b)[0]), "r"((b)[1]))

// Swizzled byte offset for 16B-unit (r, u) in a [rows][64] fp16 tile (128B rows).
__device__ __forceinline__ uint32_t swz(int r, int u) {
    return (uint32_t)(r * 128 + ((u ^ (r & 7)) << 4));
}

// Load a [rows][64] fp16 tile (chunk c of K) into smem with swizzle.
template <int ROWS>
__device__ __forceinline__ void load_tile(uint32_t sdst, const __half* g,
                                          int row0, int c, int tid) {
    #pragma unroll
    for (int j = 0; j < ROWS * 8 / 512; j++) {
        int id = j * 512 + tid;          // 16B-units
        int r = id >> 3, u = id & 7;
        const __half* src = g + (size_t)(row0 + r) * KDIM + c * BK + u * 8;
        cp16(sdst + swz(r, u), src);
    }
}

// --------------------------- prep kernels ---------------------------------

__global__ void normalize_h_kernel(const float* __restrict__ x) {
    int row = blockIdx.x;
    int t = threadIdx.x;                    // 0..63
    float4 v = ((const float4*)(x + (size_t)row * KDIM))[t];
    float s = v.x * v.x + v.y * v.y + v.z * v.z + v.w * v.w;
    #pragma unroll
    for (int o = 16; o > 0; o >>= 1) s += __shfl_xor_sync(0xffffffffu, s, o);
    __shared__ float ws[2];
    if ((t & 31) == 0) ws[t >> 5] = s;
    __syncthreads();
    float nrm = sqrtf(ws[0] + ws[1]);
    float inv = 1.0f / fmaxf(nrm, 1e-12f);
    __half2* h2 = (__half2*)(g_A + (size_t)row * KDIM + t * 4);
    h2[0] = __halves2half2(__float2half_rn(v.x * inv), __float2half_rn(v.y * inv));
    h2[1] = __halves2half2(__float2half_rn(v.z * inv), __float2half_rn(v.w * inv));
}

// Convert features to fp16 + fused fp32 passthrough copy; zero pad rows.
__global__ void feat_h_kernel(const float* __restrict__ f,
                              float* __restrict__ fcopy,
                              long total4, long total4p) {
    long i = (long)blockIdx.x * blockDim.x + threadIdx.x;
    if (i >= total4p) return;
    __half2* h2 = (__half2*)g_B;
    if (i >= total4) {
        __half2 z = __halves2half2(__float2half(0.f), __float2half(0.f));
        h2[2 * i] = z; h2[2 * i + 1] = z;
        return;
    }
    float4 v = ((const float4*)f)[i];
    ((float4*)fcopy)[i] = v;
    h2[2 * i + 0] = __halves2half2(__float2half_rn(v.x), __float2half_rn(v.y));
    h2[2 * i + 1] = __halves2half2(__float2half_rn(v.z), __float2half_rn(v.w));
}

// ------------------------------ GEMM kernel -------------------------------

__global__ __launch_bounds__(512, 1)
void gemm_mma(float* __restrict__ C, int N) {
    extern __shared__ __align__(128) char smem[];
    uint32_t sb = smem_u32(smem);

    const int tid = threadIdx.x;
    const int lane = tid & 31;
    const int wid = tid >> 5;            // 0..15
    const int m0 = blockIdx.x * BM;      // m fastest -> B tile L2 reuse
    const int n0 = blockIdx.y * BN;
    const int wm = (wid & 3) * 32;       // warp m-offset (4 slots of 32)
    const int wn = (wid >> 2) * 64;      // warp n-offset (4 slots of 64)
    const int lr = lane & 7;
    const int q  = lane >> 3;

    float acc[2][8][4];
    #pragma unroll
    for (int mt = 0; mt < 2; mt++)
        #pragma unroll
        for (int nt = 0; nt < 8; nt++)
            #pragma unroll
            for (int e = 0; e < 4; e++) acc[mt][nt][e] = 0.0f;

    // prologue: chunks 0,1,2 into stages 0,1,2
    #pragma unroll
    for (int c = 0; c < 3; c++) {
        uint32_t st = sb + c * STAGE;
        load_tile<BM>(st + T_A, g_A, m0, c, tid);
        load_tile<BN>(st + T_B, g_B, n0, c, tid);
        cp_commit();
    }

    #pragma unroll
    for (int c = 0; c < NCHUNK; c++) {
        // chunk c ready when <= (remaining groups after it) pending
        if (c <= 1)
            asm volatile("cp.async.wait_group 2;" ::: "memory");
        else if (c == 2)
            asm volatile("cp.async.wait_group 1;" ::: "memory");
        else
            asm volatile("cp.async.wait_group 0;" ::: "memory");
        __syncthreads();

        // prefetch chunk 3 into its own (virgin) stage during chunk 0 compute
        if (c == 0) {
            uint32_t st3 = sb + 3 * STAGE;
            load_tile<BM>(st3 + T_A, g_A, m0, 3, tid);
            load_tile<BN>(st3 + T_B, g_B, n0, 3, tid);
            cp_commit();
        }

        uint32_t st = sb + c * STAGE;
        uint32_t sA = st + T_A, sB = st + T_B;

        #pragma unroll
        for (int ks = 0; ks < 4; ks++) {
            uint32_t aF[2][4];
            #pragma unroll
            for (int mt = 0; mt < 2; mt++) {
                int r = wm + mt * 16 + ((q & 1) << 3) + lr;
                int u = ks * 2 + (q >> 1);
                ldmx4(aF[mt], sA + swz(r, u));
            }
            uint32_t bF[4][4];
            #pragma unroll
            for (int np = 0; np < 4; np++) {
                int r = wn + np * 16 + ((q >> 1) << 3) + lr;
                int u = ks * 2 + (q & 1);
                ldmx4(bF[np], sB + swz(r, u));
            }
            #pragma unroll
            for (int mt = 0; mt < 2; mt++) {
                #pragma unroll
                for (int nt = 0; nt < 8; nt++) {
                    uint32_t* b = &bF[nt >> 1][(nt & 1) * 2];
                    MMA(acc[mt][nt], aF[mt], b);
                }
            }
        }
    }

    // ---- epilogue: direct stores (fp32) ----
    const int r0 = lane >> 2;
    const int cq = (lane & 3) * 2;
    #pragma unroll
    for (int mt = 0; mt < 2; mt++) {
        #pragma unroll
        for (int nt = 0; nt < 8; nt++) {
            int row = m0 + wm + mt * 16 + r0;
            int col = n0 + wn + nt * 8 + cq;
            if (col < N) {
                float2 v0 = make_float2(acc[mt][nt][0], acc[mt][nt][1]);
                float2 v1 = make_float2(acc[mt][nt][2], acc[mt][nt][3]);
                *(float2*)&C[(size_t)row * N + col] = v0;
                *(float2*)&C[(size_t)(row + 8) * N + col] = v1;
            }
        }
    }
}

// ------------------------------ host side ---------------------------------

extern "C" void kernel_launch(void* const* d_in, const int* in_sizes, int n_in,
                              void* d_out, int out_size) {
    const float* x     = (const float*)d_in[0];   // [B, D]
    const float* feats = (const float*)d_in[2];   // [N, D]

    const int Bm = in_sizes[1];            // 2048
    const int D  = in_sizes[0] / Bm;       // 256
    const int N  = in_sizes[2] / D;        // 100000

    float* out = (float*)d_out;
    const size_t featE = (size_t)in_sizes[2];
    const size_t out_off = (size_t)out_size - featE;

    // 1) prep: normalize A -> fp16, B -> fp16 (+passthrough copy, zero pad)
    normalize_h_kernel<<<Bm, 64>>>(x);
    long total4  = (long)N * D / 4;
    long total4p = (long)NPAD * D / 4;
    feat_h_kernel<<<(unsigned)((total4p + 255) / 256), 256>>>(
        feats, out + out_off, total4, total4p);

    // 2) GEMM
    static int smem_set = 0;
    if (!smem_set) {
        cudaFuncSetAttribute(gemm_mma, cudaFuncAttributeMaxDynamicSharedMemorySize,
                             SMEM_TOTAL);
        smem_set = 1;
    }
    dim3 grid(Bm / BM, (N + BN - 1) / BN);   // m fastest for B-tile L2 reuse
    gemm_mma<<<grid, 512, SMEM_TOTAL>>>(out, N);
}

// round 10
// speedup vs baseline: 1.4461x; 1.4461x over previous
#include <cuda_runtime.h>
#include <cuda_fp16.h>
#include <stdint.h>
#include <stddef.h>

// ---------------------------------------------------------------------------
// out0 = normalize_rows(x) @ features^T   [2048 x 100000]  (fp32)
// out1 = features (passthrough)           [100000 x 256]
// Round 9: fp16 mma.sync GEMM (R7 shape: BM=BN=128, 2 CTAs/SM) with
// pre-tiled pre-swizzled global scratch + cp.async.bulk chunk loads
// (single-thread issue, mbarrier complete_tx). 2-stage pipeline.
// ---------------------------------------------------------------------------

#define MROWS 2048
#define KDIM  256
#define NPAD  100096      // 782 * 128

#define BM 128
#define BN 128
#define BK 64
#define NCHUNK 4          // K / BK

#define TILE_BYTES 16384  // [128 rows][64 fp16] swizzled block
#define STAGE 32768       // A block + B block
#define OFF_MBAR 65536
#define SMEM_TOTAL (65536 + 128)

// Tiled+swizzled scratch: block (tile, chunk) is contiguous 16KB.
__device__ __align__(1024) __half g_At[MROWS * KDIM];
__device__ __align__(1024) __half g_Bt[(size_t)NPAD * KDIM];

// ------------------------------ helpers -----------------------------------

__device__ __forceinline__ uint32_t smem_u32(const void* p) {
    uint32_t a;
    asm("{ .reg .u64 t; cvta.to.shared.u64 t, %1; cvt.u32.u64 %0, t; }"
        : "=r"(a) : "l"(p));
    return a;
}

__device__ __forceinline__ void mbar_init(uint32_t mbar, uint32_t cnt) {
    asm volatile("mbarrier.init.shared.b64 [%0], %1;" :: "r"(mbar), "r"(cnt) : "memory");
}
__device__ __forceinline__ void mbar_expect_tx(uint32_t mbar, uint32_t bytes) {
    asm volatile("mbarrier.arrive.expect_tx.shared.b64 _, [%0], %1;"
                 :: "r"(mbar), "r"(bytes) : "memory");
}
__device__ __forceinline__ void mbar_wait(uint32_t mbar, uint32_t parity) {
    asm volatile(
        "{\n\t.reg .pred P;\n"
        "WL_%=:\n\t"
        "mbarrier.try_wait.parity.acquire.cta.shared::cta.b64 P, [%0], %1, 0x989680;\n\t"
        "@P bra WD_%=;\n\t"
        "bra WL_%=;\n"
        "WD_%=:\n\t}"
        :: "r"(mbar), "r"(parity) : "memory");
}

// 1D bulk copy global -> shared::cta with mbarrier completion (sm_90 base).
__device__ __forceinline__ void bulk_ld(uint32_t dst, const void* src,
                                        uint32_t bytes, uint32_t mbar) {
    asm volatile(
        "cp.async.bulk.shared::cta.global.mbarrier::complete_tx::bytes "
        "[%0], [%1], %2, [%3];"
        :: "r"(dst), "l"(src), "r"(bytes), "r"(mbar) : "memory");
}

__device__ __forceinline__ void ldmx4(uint32_t* f, uint32_t addr) {
    asm volatile("ldmatrix.sync.aligned.m8n8.x4.shared.b16 {%0,%1,%2,%3}, [%4];"
                 : "=r"(f[0]), "=r"(f[1]), "=r"(f[2]), "=r"(f[3]) : "r"(addr));
}

#define MMA(c, a, b)                                                          \
    asm volatile(                                                             \
        "mma.sync.aligned.m16n8k16.row.col.f32.f16.f16.f32 "                  \
        "{%0,%1,%2,%3},{%4,%5,%6,%7},{%8,%9},{%0,%1,%2,%3};"                  \
        : "+f"((c)[0]), "+f"((c)[1]), "+f"((c)[2]), "+f"((c)[3])              \
        : "r"((a)[0]), "r"((a)[1]), "r"((a)[2]), "r"((a)[3]),                 \
          "r"((b)[0]), "r"((b)[1]))

// Swizzled byte offset for 16B-unit (r, u) in a [128][64] fp16 tile (128B rows).
__device__ __host__ __forceinline__ uint32_t swz(int r, int u) {
    return (uint32_t)(r * 128 + ((u ^ (r & 7)) << 4));
}

// --------------------------- prep kernels ---------------------------------

// One warp per row: normalize + fp16 convert + write into tiled/swizzled g_At.
__global__ void normalize_h_kernel(const float* __restrict__ x) {
    int row = blockIdx.x;
    int t = threadIdx.x;                    // 0..31, each owns 8 floats
    const float4* xr = (const float4*)(x + (size_t)row * KDIM);
    float4 v0 = xr[2 * t], v1 = xr[2 * t + 1];
    float s = v0.x * v0.x + v0.y * v0.y + v0.z * v0.z + v0.w * v0.w
            + v1.x * v1.x + v1.y * v1.y + v1.z * v1.z + v1.w * v1.w;
    #pragma unroll
    for (int o = 16; o > 0; o >>= 1) s += __shfl_xor_sync(0xffffffffu, s, o);
    float inv = 1.0f / fmaxf(sqrtf(s), 1e-12f);

    uint32_t h[4];
    __half2* hp = (__half2*)h;
    hp[0] = __halves2half2(__float2half_rn(v0.x * inv), __float2half_rn(v0.y * inv));
    hp[1] = __halves2half2(__float2half_rn(v0.z * inv), __float2half_rn(v0.w * inv));
    hp[2] = __halves2half2(__float2half_rn(v1.x * inv), __float2half_rn(v1.y * inv));
    hp[3] = __halves2half2(__float2half_rn(v1.z * inv), __float2half_rn(v1.w * inv));

    int k0 = t * 8;
    int blk = (row >> 7) * NCHUNK + (k0 >> 6);
    uint32_t off = (uint32_t)blk * TILE_BYTES + swz(row & 127, (k0 & 63) >> 3);
    *(uint4*)((char*)g_At + off) = *(uint4*)h;
}

// features -> fp16 tiled/swizzled g_Bt + fused fp32 passthrough copy.
// One thread per 16B output unit (8 k-values of one row).
__global__ void feat_h_kernel(const float* __restrict__ f,
                              float* __restrict__ fcopy, int N) {
    long i = (long)blockIdx.x * blockDim.x + threadIdx.x;   // < NPAD*32
    int n = (int)(i >> 5);
    int j = (int)(i & 31);
    int k0 = j * 8;

    uint32_t h[4];
    if (n < N) {
        const float4* fr = (const float4*)(f + (size_t)n * KDIM + k0);
        float4 v0 = fr[0], v1 = fr[1];
        float4* cp = (float4*)(fcopy + (size_t)n * KDIM + k0);
        cp[0] = v0; cp[1] = v1;
        __half2* hp = (__half2*)h;
        hp[0] = __halves2half2(__float2half_rn(v0.x), __float2half_rn(v0.y));
        hp[1] = __halves2half2(__float2half_rn(v0.z), __float2half_rn(v0.w));
        hp[2] = __halves2half2(__float2half_rn(v1.x), __float2half_rn(v1.y));
        hp[3] = __halves2half2(__float2half_rn(v1.z), __float2half_rn(v1.w));
    } else {
        h[0] = h[1] = h[2] = h[3] = 0u;
    }
    int blk = (n >> 7) * NCHUNK + (k0 >> 6);
    uint32_t off_in = swz(n & 127, (k0 & 63) >> 3);
    *(uint4*)((char*)g_Bt + (size_t)blk * TILE_BYTES + off_in) = *(uint4*)h;
}

// ------------------------------ GEMM kernel -------------------------------

__global__ __launch_bounds__(256, 2)
void gemm_mma(float* __restrict__ C, int N) {
    extern __shared__ __align__(128) char smem[];
    uint32_t sb = smem_u32(smem);

    const int tid = threadIdx.x;
    const int lane = tid & 31;
    const int wid = tid >> 5;
    const int mt = blockIdx.x;           // m fastest -> B tile L2 reuse
    const int nt = blockIdx.y;
    const int m0 = mt * BM;
    const int n0 = nt * BN;
    const int am = (wid & 1) * 64;       // warp m-offset
    const int bn = (wid >> 1) * 32;      // warp n-offset
    const int lr = lane & 7;
    const int q  = lane >> 3;

    const char* gA = (const char*)g_At + (size_t)mt * NCHUNK * TILE_BYTES;
    const char* gB = (const char*)g_Bt + (size_t)nt * NCHUNK * TILE_BYTES;

    const uint32_t full0 = sb + OFF_MBAR;
    const uint32_t full1 = sb + OFF_MBAR + 8;

    if (tid == 0) {
        mbar_init(full0, 1);
        mbar_init(full1, 1);
    }
    __syncthreads();

    if (tid == 0) {
        mbar_expect_tx(full0, STAGE);
        bulk_ld(sb,                 gA + 0 * TILE_BYTES, TILE_BYTES, full0);
        bulk_ld(sb + TILE_BYTES,    gB + 0 * TILE_BYTES, TILE_BYTES, full0);
        mbar_expect_tx(full1, STAGE);
        bulk_ld(sb + STAGE,              gA + 1 * TILE_BYTES, TILE_BYTES, full1);
        bulk_ld(sb + STAGE + TILE_BYTES, gB + 1 * TILE_BYTES, TILE_BYTES, full1);
    }

    float acc[4][4][4];
    #pragma unroll
    for (int mtt = 0; mtt < 4; mtt++)
        #pragma unroll
        for (int ntt = 0; ntt < 4; ntt++)
            #pragma unroll
            for (int e = 0; e < 4; e++) acc[mtt][ntt][e] = 0.0f;

    #pragma unroll
    for (int c = 0; c < NCHUNK; c++) {
        const int s = c & 1;
        mbar_wait(s ? full1 : full0, (c >> 1) & 1);

        uint32_t st = sb + s * STAGE;
        uint32_t sA = st, sB = st + TILE_BYTES;

        #pragma unroll
        for (int ks = 0; ks < 4; ks++) {
            uint32_t aF[4][4];
            #pragma unroll
            for (int mtt = 0; mtt < 4; mtt++) {
                int r = am + mtt * 16 + ((q & 1) << 3) + lr;
                int u = ks * 2 + (q >> 1);
                ldmx4(aF[mtt], sA + swz(r, u));
            }
            uint32_t bF[2][4];
            #pragma unroll
            for (int np = 0; np < 2; np++) {
                int r = bn + np * 16 + ((q >> 1) << 3) + lr;
                int u = ks * 2 + (q & 1);
                ldmx4(bF[np], sB + swz(r, u));
            }
            #pragma unroll
            for (int mtt = 0; mtt < 4; mtt++) {
                #pragma unroll
                for (int ntt = 0; ntt < 4; ntt++) {
                    uint32_t* b = &bF[ntt >> 1][(ntt & 1) * 2];
                    MMA(acc[mtt][ntt], aF[mtt], b);
                }
            }
        }

        // Recycle this stage for chunk c+2 (barrier: all warps done reading).
        if (c < NCHUNK - 2) {
            __syncthreads();
            if (tid == 0) {
                uint32_t fb = s ? full1 : full0;
                int c2 = c + 2;
                mbar_expect_tx(fb, STAGE);
                bulk_ld(st,              gA + c2 * TILE_BYTES, TILE_BYTES, fb);
                bulk_ld(st + TILE_BYTES, gB + c2 * TILE_BYTES, TILE_BYTES, fb);
            }
        }
    }

    // ---- epilogue: direct stores (fp32) ----
    const int r0 = lane >> 2;
    const int cq = (lane & 3) * 2;
    #pragma unroll
    for (int mtt = 0; mtt < 4; mtt++) {
        #pragma unroll
        for (int ntt = 0; ntt < 4; ntt++) {
            int row = m0 + am + mtt * 16 + r0;
            int col = n0 + bn + ntt * 8 + cq;
            if (col < N) {
                float2 v0 = make_float2(acc[mtt][ntt][0], acc[mtt][ntt][1]);
                float2 v1 = make_float2(acc[mtt][ntt][2], acc[mtt][ntt][3]);
                *(float2*)&C[(size_t)row * N + col] = v0;
                *(float2*)&C[(size_t)(row + 8) * N + col] = v1;
            }
        }
    }
}

// ------------------------------ host side ---------------------------------

extern "C" void kernel_launch(void* const* d_in, const int* in_sizes, int n_in,
                              void* d_out, int out_size) {
    const float* x     = (const float*)d_in[0];   // [B, D]
    const float* feats = (const float*)d_in[2];   // [N, D]

    const int Bm = in_sizes[1];            // 2048
    const int D  = in_sizes[0] / Bm;       // 256
    const int N  = in_sizes[2] / D;        // 100000

    float* out = (float*)d_out;
    const size_t featE = (size_t)in_sizes[2];
    const size_t out_off = (size_t)out_size - featE;

    // 1) prep: normalize A -> tiled fp16, B -> tiled fp16 (+passthrough copy)
    normalize_h_kernel<<<Bm, 32>>>(x);
    long units = (long)NPAD * 32;          // 16B units in g_Bt
    feat_h_kernel<<<(unsigned)((units + 255) / 256), 256>>>(
        feats, out + out_off, N);

    // 2) GEMM
    static int smem_set = 0;
    if (!smem_set) {
        cudaFuncSetAttribute(gemm_mma, cudaFuncAttributeMaxDynamicSharedMemorySize,
                             SMEM_TOTAL);
        smem_set = 1;
    }
    dim3 grid(Bm / BM, (N + BN - 1) / BN);   // m fastest for B-tile L2 reuse
    gemm_mma<<<grid, 256, SMEM_TOTAL>>>(out, N);
}

// round 11
// speedup vs baseline: 1.4792x; 1.0229x over previous
#include <cuda_runtime.h>
#include <cuda_fp16.h>
#include <stdint.h>
#include <stddef.h>

// ---------------------------------------------------------------------------
// out0 = normalize_rows(x) @ features^T   [2048 x 100000]  (fp32)
// out1 = features (passthrough)           [100000 x 256]
// Round 10: fp16 mma.sync GEMM, pre-tiled swizzled scratch, cp.async.bulk,
// 3 smem stages (one barrier in mainloop), passthrough copy fused into GEMM.
// ---------------------------------------------------------------------------

#define MROWS 2048
#define KDIM  256
#define NPAD  100096      // 782 * 128

#define BM 128
#define BN 128
#define BK 64
#define NCHUNK 4          // K / BK

#define TILE_BYTES 16384  // [128 rows][64 fp16] swizzled block
#define STAGE 32768       // A block + B block
#define OFF_MBAR 98304
#define SMEM_TOTAL (98304 + 128)

// Tiled+swizzled scratch: block (tile, chunk) is contiguous 16KB.
__device__ __align__(1024) __half g_At[MROWS * KDIM];
__device__ __align__(1024) __half g_Bt[(size_t)NPAD * KDIM];

// ------------------------------ helpers -----------------------------------

__device__ __forceinline__ uint32_t smem_u32(const void* p) {
    uint32_t a;
    asm("{ .reg .u64 t; cvta.to.shared.u64 t, %1; cvt.u32.u64 %0, t; }"
        : "=r"(a) : "l"(p));
    return a;
}

__device__ __forceinline__ void mbar_init(uint32_t mbar, uint32_t cnt) {
    asm volatile("mbarrier.init.shared.b64 [%0], %1;" :: "r"(mbar), "r"(cnt) : "memory");
}
__device__ __forceinline__ void mbar_expect_tx(uint32_t mbar, uint32_t bytes) {
    asm volatile("mbarrier.arrive.expect_tx.shared.b64 _, [%0], %1;"
                 :: "r"(mbar), "r"(bytes) : "memory");
}
__device__ __forceinline__ void mbar_wait(uint32_t mbar, uint32_t parity) {
    asm volatile(
        "{\n\t.reg .pred P;\n"
        "WL_%=:\n\t"
        "mbarrier.try_wait.parity.acquire.cta.shared::cta.b64 P, [%0], %1, 0x989680;\n\t"
        "@P bra WD_%=;\n\t"
        "bra WL_%=;\n"
        "WD_%=:\n\t}"
        :: "r"(mbar), "r"(parity) : "memory");
}

// 1D bulk copy global -> shared::cta with mbarrier completion (sm_90 base).
__device__ __forceinline__ void bulk_ld(uint32_t dst, const void* src,
                                        uint32_t bytes, uint32_t mbar) {
    asm volatile(
        "cp.async.bulk.shared::cta.global.mbarrier::complete_tx::bytes "
        "[%0], [%1], %2, [%3];"
        :: "r"(dst), "l"(src), "r"(bytes), "r"(mbar) : "memory");
}

__device__ __forceinline__ void ldmx4(uint32_t* f, uint32_t addr) {
    asm volatile("ldmatrix.sync.aligned.m8n8.x4.shared.b16 {%0,%1,%2,%3}, [%4];"
                 : "=r"(f[0]), "=r"(f[1]), "=r"(f[2]), "=r"(f[3]) : "r"(addr));
}

#define MMA(c, a, b)                                                          \
    asm volatile(                                                             \
        "mma.sync.aligned.m16n8k16.row.col.f32.f16.f16.f32 "                  \
        "{%0,%1,%2,%3},{%4,%5,%6,%7},{%8,%9},{%0,%1,%2,%3};"                  \
        : "+f"((c)[0]), "+f"((c)[1]), "+f"((c)[2]), "+f"((c)[3])              \
        : "r"((a)[0]), "r"((a)[1]), "r"((a)[2]), "r"((a)[3]),                 \
          "r"((b)[0]), "r"((b)[1]))

// Swizzled byte offset for 16B-unit (r, u) in a [128][64] fp16 tile (128B rows).
__device__ __host__ __forceinline__ uint32_t swz(int r, int u) {
    return (uint32_t)(r * 128 + ((u ^ (r & 7)) << 4));
}

// --------------------------- prep kernels ---------------------------------

// One warp per row: normalize + fp16 convert + write into tiled/swizzled g_At.
__global__ void normalize_h_kernel(const float* __restrict__ x) {
    int row = blockIdx.x;
    int t = threadIdx.x;                    // 0..31, each owns 8 floats
    const float4* xr = (const float4*)(x + (size_t)row * KDIM);
    float4 v0 = xr[2 * t], v1 = xr[2 * t + 1];
    float s = v0.x * v0.x + v0.y * v0.y + v0.z * v0.z + v0.w * v0.w
            + v1.x * v1.x + v1.y * v1.y + v1.z * v1.z + v1.w * v1.w;
    #pragma unroll
    for (int o = 16; o > 0; o >>= 1) s += __shfl_xor_sync(0xffffffffu, s, o);
    float inv = 1.0f / fmaxf(sqrtf(s), 1e-12f);

    uint32_t h[4];
    __half2* hp = (__half2*)h;
    hp[0] = __halves2half2(__float2half_rn(v0.x * inv), __float2half_rn(v0.y * inv));
    hp[1] = __halves2half2(__float2half_rn(v0.z * inv), __float2half_rn(v0.w * inv));
    hp[2] = __halves2half2(__float2half_rn(v1.x * inv), __float2half_rn(v1.y * inv));
    hp[3] = __halves2half2(__float2half_rn(v1.z * inv), __float2half_rn(v1.w * inv));

    int k0 = t * 8;
    int blk = (row >> 7) * NCHUNK + (k0 >> 6);
    uint32_t off = (uint32_t)blk * TILE_BYTES + swz(row & 127, (k0 & 63) >> 3);
    *(uint4*)((char*)g_At + off) = *(uint4*)h;
}

// features -> fp16 tiled/swizzled g_Bt (copy moved into GEMM). Zero pad rows.
__global__ void feat_h_kernel(const float* __restrict__ f, int N) {
    long i = (long)blockIdx.x * blockDim.x + threadIdx.x;   // < NPAD*32
    int n = (int)(i >> 5);
    int j = (int)(i & 31);
    int k0 = j * 8;

    uint32_t h[4];
    if (n < N) {
        const float4* fr = (const float4*)(f + (size_t)n * KDIM + k0);
        float4 v0 = fr[0], v1 = fr[1];
        __half2* hp = (__half2*)h;
        hp[0] = __halves2half2(__float2half_rn(v0.x), __float2half_rn(v0.y));
        hp[1] = __halves2half2(__float2half_rn(v0.z), __float2half_rn(v0.w));
        hp[2] = __halves2half2(__float2half_rn(v1.x), __float2half_rn(v1.y));
        hp[3] = __halves2half2(__float2half_rn(v1.z), __float2half_rn(v1.w));
    } else {
        h[0] = h[1] = h[2] = h[3] = 0u;
    }
    int blk = (n >> 7) * NCHUNK + (k0 >> 6);
    uint32_t off_in = swz(n & 127, (k0 & 63) >> 3);
    *(uint4*)((char*)g_Bt + (size_t)blk * TILE_BYTES + off_in) = *(uint4*)h;
}

// ------------------------------ GEMM kernel -------------------------------

__global__ __launch_bounds__(256, 2)
void gemm_mma(float* __restrict__ C, int N,
              const float* __restrict__ feats, float* __restrict__ fcopy,
              long copy4_total) {
    extern __shared__ __align__(128) char smem[];
    uint32_t sb = smem_u32(smem);

    const int tid = threadIdx.x;
    const int lane = tid & 31;
    const int wid = tid >> 5;
    const int mt = blockIdx.x;           // m fastest -> B tile L2 reuse
    const int nt = blockIdx.y;
    const int m0 = mt * BM;
    const int n0 = nt * BN;
    const int am = (wid & 1) * 64;       // warp m-offset
    const int bn = (wid >> 1) * 32;      // warp n-offset
    const int lr = lane & 7;
    const int q  = lane >> 3;

    const char* gA = (const char*)g_At + (size_t)mt * NCHUNK * TILE_BYTES;
    const char* gB = (const char*)g_Bt + (size_t)nt * NCHUNK * TILE_BYTES;

    const uint32_t full0 = sb + OFF_MBAR;
    const uint32_t full1 = sb + OFF_MBAR + 8;
    const uint32_t full2 = sb + OFF_MBAR + 16;

    if (tid == 0) {
        mbar_init(full0, 1);
        mbar_init(full1, 1);
        mbar_init(full2, 1);
    }
    __syncthreads();

    // prologue: chunks 0,1,2 into stages 0,1,2
    if (tid == 0) {
        #pragma unroll
        for (int c = 0; c < 3; c++) {
            uint32_t fb = full0 + 8 * c;
            uint32_t st = sb + c * STAGE;
            mbar_expect_tx(fb, STAGE);
            bulk_ld(st,              gA + c * TILE_BYTES, TILE_BYTES, fb);
            bulk_ld(st + TILE_BYTES, gB + c * TILE_BYTES, TILE_BYTES, fb);
        }
    }

    // fused passthrough copy: this CTA's slice of features -> fcopy.
    // Overlaps with prologue loads + early compute (DRAM pipe is idle here).
    {
        long base = (long)(nt * gridDim.x + mt) * 1024;
        const float4* src = (const float4*)feats;
        float4* dst = (float4*)fcopy;
        #pragma unroll
        for (int it = 0; it < 4; it++) {
            long idx = base + it * 256 + tid;
            if (idx < copy4_total) dst[idx] = src[idx];
        }
    }

    float acc[4][4][4];
    #pragma unroll
    for (int mtt = 0; mtt < 4; mtt++)
        #pragma unroll
        for (int ntt = 0; ntt < 4; ntt++)
            #pragma unroll
            for (int e = 0; e < 4; e++) acc[mtt][ntt][e] = 0.0f;

    #pragma unroll
    for (int c = 0; c < NCHUNK; c++) {
        const int s = c % 3;
        mbar_wait(full0 + 8 * s, (c >= 3) ? 1 : 0);

        uint32_t st = sb + s * STAGE;
        uint32_t sA = st, sB = st + TILE_BYTES;

        #pragma unroll
        for (int ks = 0; ks < 4; ks++) {
            uint32_t aF[4][4];
            #pragma unroll
            for (int mtt = 0; mtt < 4; mtt++) {
                int r = am + mtt * 16 + ((q & 1) << 3) + lr;
                int u = ks * 2 + (q >> 1);
                ldmx4(aF[mtt], sA + swz(r, u));
            }
            uint32_t bF[2][4];
            #pragma unroll
            for (int np = 0; np < 2; np++) {
                int r = bn + np * 16 + ((q >> 1) << 3) + lr;
                int u = ks * 2 + (q & 1);
                ldmx4(bF[np], sB + swz(r, u));
            }
            #pragma unroll
            for (int mtt = 0; mtt < 4; mtt++) {
                #pragma unroll
                for (int ntt = 0; ntt < 4; ntt++) {
                    uint32_t* b = &bF[ntt >> 1][(ntt & 1) * 2];
                    MMA(acc[mtt][ntt], aF[mtt], b);
                }
            }
        }

        // After chunk 0: stage 0 is free; load chunk 3 into it.
        if (c == 0) {
            __syncthreads();            // all warps done reading stage 0
            if (tid == 0) {
                mbar_expect_tx(full0, STAGE);
                bulk_ld(st,              gA + 3 * TILE_BYTES, TILE_BYTES, full0);
                bulk_ld(st + TILE_BYTES, gB + 3 * TILE_BYTES, TILE_BYTES, full0);
            }
        }
    }

    // ---- epilogue: direct stores (fp32) ----
    const int r0 = lane >> 2;
    const int cq = (lane & 3) * 2;
    #pragma unroll
    for (int mtt = 0; mtt < 4; mtt++) {
        #pragma unroll
        for (int ntt = 0; ntt < 4; ntt++) {
            int row = m0 + am + mtt * 16 + r0;
            int col = n0 + bn + ntt * 8 + cq;
            if (col < N) {
                float2 v0 = make_float2(acc[mtt][ntt][0], acc[mtt][ntt][1]);
                float2 v1 = make_float2(acc[mtt][ntt][2], acc[mtt][ntt][3]);
                *(float2*)&C[(size_t)row * N + col] = v0;
                *(float2*)&C[(size_t)(row + 8) * N + col] = v1;
            }
        }
    }
}

// ------------------------------ host side ---------------------------------

extern "C" void kernel_launch(void* const* d_in, const int* in_sizes, int n_in,
                              void* d_out, int out_size) {
    const float* x     = (const float*)d_in[0];   // [B, D]
    const float* feats = (const float*)d_in[2];   // [N, D]

    const int Bm = in_sizes[1];            // 2048
    const int D  = in_sizes[0] / Bm;       // 256
    const int N  = in_sizes[2] / D;        // 100000

    float* out = (float*)d_out;
    const size_t featE = (size_t)in_sizes[2];
    const size_t out_off = (size_t)out_size - featE;

    // 1) prep: normalize A -> tiled fp16, B -> tiled fp16
    normalize_h_kernel<<<Bm, 32>>>(x);
    long units = (long)NPAD * 32;          // 16B units in g_Bt
    feat_h_kernel<<<(unsigned)((units + 255) / 256), 256>>>(feats, N);

    // 2) GEMM + fused passthrough copy
    static int smem_set = 0;
    if (!smem_set) {
        cudaFuncSetAttribute(gemm_mma, cudaFuncAttributeMaxDynamicSharedMemorySize,
                             SMEM_TOTAL);
        smem_set = 1;
    }
    long copy4_total = (long)featE / 4;
    dim3 grid(Bm / BM, (N + BN - 1) / BN);   // m fastest for B-tile L2 reuse
    gemm_mma<<<grid, 256, SMEM_TOTAL>>>(out, N, feats, out + out_off, copy4_total);
}